// round 1
// baseline (speedup 1.0000x reference)
#include <cuda_runtime.h>
#include <cfloat>

#define Nn 100000
#define NnP 100032          // padded to multiple of 64 and 48
#define Ee 1600000
#define Dd 64
#define Gg 512
#define OUTD 16
#define NL 5
#define DELTA 2.5749f
#define BN_EPS 1e-5f

// ---------------- static device scratch (no allocation allowed) ----------------
static __device__ float g_hA[NnP * Dd];        // current h
static __device__ float g_hB[NnP * Dd];        // hmid / u
static __device__ float g_hC[NnP * Dd];        // t
static __device__ float g_base[NnP * 4 * Dd];  // [sum|max|mean|var]
static __device__ float g_S[NnP * 192];
static __device__ float g_cfac[NnP];
static __device__ int   g_deg[Nn];
static __device__ int   g_sc[Nn];
static __device__ int   g_bsum[128];
static __device__ int   g_rowptr[Nn + 1];
static __device__ int   g_cursor[Nn];
static __device__ int   g_esrc[Ee];
static __device__ float g_part[Gg * 2 * Dd];
static __device__ float g_scale[Dd];
static __device__ float g_shift[Dd];
static __device__ int   g_bstart[Gg + 1];
static __device__ float g_gpool[Gg * Dd];
static __device__ float g_encWt[Dd * Dd];
static __device__ float g_nnW1t[NL * Dd * Dd];
static __device__ float g_nnW2t[NL * Dd * Dd];
static __device__ float g_mlpWt[NL * 256 * 192];
static __device__ float g_fc1Wt[Dd * Dd];
static __device__ float g_fc2Wt[Dd * OUTD];

// ---------------- CSR build ----------------
__global__ void k_zero_deg() {
    int i = blockIdx.x * blockDim.x + threadIdx.x;
    if (i < Nn) g_deg[i] = 0;
}

__global__ void k_count(const int* __restrict__ dst) {
    int e = blockIdx.x * blockDim.x + threadIdx.x;
    if (e < Ee) atomicAdd(&g_deg[dst[e]], 1);
}

__global__ void k_scan_block() {
    __shared__ int sm[1024];
    int i = blockIdx.x * 1024 + threadIdx.x;
    int v = (i < Nn) ? g_deg[i] : 0;
    sm[threadIdx.x] = v;
    __syncthreads();
    for (int off = 1; off < 1024; off <<= 1) {
        int t = 0;
        if (threadIdx.x >= off) t = sm[threadIdx.x - off];
        __syncthreads();
        sm[threadIdx.x] += t;
        __syncthreads();
    }
    if (i < Nn) g_sc[i] = sm[threadIdx.x];
    if (threadIdx.x == 1023) g_bsum[blockIdx.x] = sm[1023];
}

__global__ void k_scan_tops(int nb) {
    if (threadIdx.x == 0 && blockIdx.x == 0) {
        int run = 0;
        for (int b = 0; b < nb; b++) {
            int t = g_bsum[b];
            g_bsum[b] = run;
            run += t;
        }
    }
}

__global__ void k_rowptr() {
    int i = blockIdx.x * blockDim.x + threadIdx.x;
    if (i < Nn) {
        int rp = g_sc[i] - g_deg[i] + g_bsum[i >> 10];
        g_rowptr[i] = rp;
        g_cursor[i] = rp;
    }
    if (i == 0) g_rowptr[Nn] = Ee;
}

__global__ void k_scatter(const int* __restrict__ src, const int* __restrict__ dst) {
    int e = blockIdx.x * blockDim.x + threadIdx.x;
    if (e < Ee) {
        int d0 = dst[e];
        int p = atomicAdd(&g_cursor[d0], 1);
        g_esrc[p] = src[e];
    }
}

// deterministic within-row order (insertion sort; ties are identical values)
__global__ void k_sortrows() {
    int n = blockIdx.x * blockDim.x + threadIdx.x;
    if (n >= Nn) return;
    int beg = g_rowptr[n], end = g_rowptr[n + 1];
    for (int i = beg + 1; i < end; i++) {
        int v = g_esrc[i];
        int j = i - 1;
        while (j >= beg && g_esrc[j] > v) { g_esrc[j + 1] = g_esrc[j]; j--; }
        g_esrc[j + 1] = v;
    }
    float dg = (float)(end - beg);
    g_cfac[n] = fmaxf(dg, 1.0f);
}

// ---------------- weight transposes ----------------
// Wt[m][k*64+d] = W[m][d*64+k]
__global__ void k_t64(const float* __restrict__ W, float* __restrict__ Wt, int nm) {
    int idx = blockIdx.x * blockDim.x + threadIdx.x;
    if (idx >= nm * 4096) return;
    int m = idx >> 12, r = idx & 4095;
    int d = r >> 6, k = r & 63;
    Wt[(m << 12) + (k << 6) + d] = W[idx];
}

// mlpWt[m][k*192 + 64*b + d] = mlpW[m][d*768 + 256*b + k]
__global__ void k_tmlp(const float* __restrict__ W) {
    int idx = blockIdx.x * blockDim.x + threadIdx.x;
    if (idx >= NL * 49152) return;
    int m = idx / 49152, r = idx % 49152;
    int d = r / 768, col = r % 768;
    int b = col >> 8, k = col & 255;
    g_mlpWt[m * 49152 + k * 192 + (b << 6) + d] = W[idx];
}

__global__ void k_tfc2(const float* __restrict__ W) {
    int idx = blockIdx.x * blockDim.x + threadIdx.x;
    if (idx >= Dd * OUTD) return;
    int o = idx >> 6, k = idx & 63;
    g_fc2Wt[k * 16 + o] = W[idx];
}

// ---------------- generic 64x64 linear: C = act(A @ Wt + b) ----------------
template <bool RELU>
__global__ void __launch_bounds__(64) k_lin64(const float* __restrict__ A,
                                              const float* __restrict__ Wt,
                                              const float* __restrict__ b,
                                              float* __restrict__ C) {
    __shared__ float4 Asm[64][16];
    int row0 = blockIdx.x * 64, tid = threadIdx.x;
    for (int t = tid; t < 1024; t += 64) {
        int r = t >> 4, c = t & 15;
        float4 v = make_float4(0.f, 0.f, 0.f, 0.f);
        if (row0 + r < Nn) v = ((const float4*)A)[(row0 + r) * 16 + c];
        Asm[r][c] = v;
    }
    __syncthreads();
    float acc[64];
#pragma unroll
    for (int r = 0; r < 64; r++) acc[r] = 0.f;
#pragma unroll 1
    for (int k4 = 0; k4 < 16; k4++) {
        float w0 = Wt[(k4 * 4 + 0) * 64 + tid];
        float w1 = Wt[(k4 * 4 + 1) * 64 + tid];
        float w2 = Wt[(k4 * 4 + 2) * 64 + tid];
        float w3 = Wt[(k4 * 4 + 3) * 64 + tid];
#pragma unroll
        for (int r = 0; r < 64; r++) {
            float4 a = Asm[r][k4];
            float t0 = fmaf(a.x, w0, acc[r]);
            t0 = fmaf(a.y, w1, t0);
            t0 = fmaf(a.z, w2, t0);
            acc[r] = fmaf(a.w, w3, t0);
        }
    }
    float bb = b[tid];
    for (int r = 0; r < 64; r++) {
        if (row0 + r < Nn) {
            float v = acc[r] + bb;
            if (RELU) v = fmaxf(v, 0.f);
            C[(row0 + r) * 64 + tid] = v;
        }
    }
}

// ---------------- PNA aggregation (CSR gather, warp per node) ----------------
__global__ void k_agg() {
    int gt = blockIdx.x * blockDim.x + threadIdx.x;
    int w = gt >> 5, lane = gt & 31;
    if (w >= Nn) return;
    int beg = g_rowptr[w], end = g_rowptr[w + 1];
    const float2* hp = (const float2*)g_hA;
    float sx = 0.f, sy = 0.f, qx = 0.f, qy = 0.f;
    float mxx = -FLT_MAX, mxy = -FLT_MAX;
    for (int j = beg; j < end; j++) {
        int s = g_esrc[j];
        float2 v = hp[s * 32 + lane];
        sx += v.x; sy += v.y;
        qx = fmaf(v.x, v.x, qx);
        qy = fmaf(v.y, v.y, qy);
        mxx = fmaxf(mxx, v.x);
        mxy = fmaxf(mxy, v.y);
    }
    if (end == beg) { mxx = 0.f; mxy = 0.f; }
    float c = g_cfac[w];
    float inv = 1.f / c;
    float mex = sx * inv, mey = sy * inv;
    float vx = fmaxf(qx * inv - mex * mex, 0.f);
    float vy = fmaxf(qy * inv - mey * mey, 0.f);
    float2* bp = (float2*)(g_base + (size_t)w * 256);
    bp[lane]      = make_float2(sx, sy);
    bp[32 + lane] = make_float2(mxx, mxy);
    bp[64 + lane] = make_float2(mex, mey);
    bp[96 + lane] = make_float2(vx, vy);
}

// ---------------- S = base[N,256] @ mlpWt[256,192] ----------------
__global__ void __launch_bounds__(192) k_gemmS(const float* __restrict__ Wt) {
    __shared__ float4 Bsm[48][64];  // 48 rows x 256 floats = 48KB
    int row0 = blockIdx.x * 48, tid = threadIdx.x;
    for (int t = tid; t < 48 * 64; t += 192) {
        int r = t >> 6, c = t & 63;
        Bsm[r][c] = ((const float4*)g_base)[(row0 + r) * 64 + c];
    }
    __syncthreads();
    float acc[48];
#pragma unroll
    for (int r = 0; r < 48; r++) acc[r] = 0.f;
#pragma unroll 1
    for (int k4 = 0; k4 < 64; k4++) {
        float w0 = Wt[(k4 * 4 + 0) * 192 + tid];
        float w1 = Wt[(k4 * 4 + 1) * 192 + tid];
        float w2 = Wt[(k4 * 4 + 2) * 192 + tid];
        float w3 = Wt[(k4 * 4 + 3) * 192 + tid];
#pragma unroll
        for (int r = 0; r < 48; r++) {
            float4 a = Bsm[r][k4];
            float t0 = fmaf(a.x, w0, acc[r]);
            t0 = fmaf(a.y, w1, t0);
            t0 = fmaf(a.z, w2, t0);
            acc[r] = fmaf(a.w, w3, t0);
        }
    }
    for (int r = 0; r < 48; r++) g_S[(row0 + r) * 192 + tid] = acc[r];
}

// ---------------- combine: hB = hA + S0 + (c/D)S1 + (D/c)S2 + mb ----------------
__global__ void k_combine(const float* __restrict__ mb) {
    int idx = blockIdx.x * blockDim.x + threadIdx.x;
    if (idx >= Nn * Dd) return;
    int n = idx >> 6, d = idx & 63;
    float c = g_cfac[n];
    float a = c * (1.0f / DELTA);
    float b2 = DELTA / c;
    const float* Sr = g_S + n * 192;
    float v = g_hA[idx] + mb[d] + Sr[d] + a * Sr[64 + d] + b2 * Sr[128 + d];
    g_hB[idx] = v;
}

// ---------------- batchnorm (deterministic two-level) ----------------
#define BN_CHUNK ((Nn + Gg - 1) / Gg)  // 196
__global__ void k_bnpart() {
    int b = blockIdx.x, d = threadIdx.x;
    int r0 = b * BN_CHUNK;
    int r1 = min(r0 + BN_CHUNK, Nn);
    float s = 0.f, q = 0.f;
    for (int r = r0; r < r1; r++) {
        float v = g_hB[r * 64 + d];
        s += v;
        q = fmaf(v, v, q);
    }
    g_part[b * 128 + d] = s;
    g_part[b * 128 + 64 + d] = q;
}

__global__ void k_bnfin(const float* __restrict__ gamma, const float* __restrict__ beta) {
    int d = threadIdx.x;
    float s = 0.f, q = 0.f;
    for (int b = 0; b < Gg; b++) {
        s += g_part[b * 128 + d];
        q += g_part[b * 128 + 64 + d];
    }
    float mean = s * (1.0f / Nn);
    float var = q * (1.0f / Nn) - mean * mean;
    float sc = gamma[d] * rsqrtf(var + BN_EPS);
    g_scale[d] = sc;
    g_shift[d] = fmaf(-mean, sc, beta[d]);
}

__global__ void k_bnapply() {
    int idx = blockIdx.x * blockDim.x + threadIdx.x;
    if (idx >= Nn * Dd) return;
    int d = idx & 63;
    g_hA[idx] = fmaf(g_hB[idx], g_scale[d], g_shift[d]);
}

// ---------------- pooling + head ----------------
__global__ void k_bounds(const int* __restrict__ batch) {
    int g = blockIdx.x * blockDim.x + threadIdx.x;
    if (g > Gg) return;
    if (g == Gg) { g_bstart[Gg] = Nn; return; }
    int lo = 0, hi = Nn;
    while (lo < hi) {
        int mid = (lo + hi) >> 1;
        if (batch[mid] < g) lo = mid + 1; else hi = mid;
    }
    g_bstart[g] = lo;
}

__global__ void k_pool() {
    int g = blockIdx.x, d = threadIdx.x;
    int r0 = g_bstart[g], r1 = g_bstart[g + 1];
    float s = 0.f;
    for (int r = r0; r < r1; r++) s += g_hA[r * 64 + d];
    g_gpool[g * 64 + d] = s;
}

__global__ void k_head(const float* __restrict__ fc1b, const float* __restrict__ fc2b,
                       float* __restrict__ out) {
    __shared__ float gsm[64], tsm[64];
    int g = blockIdx.x, d = threadIdx.x;
    gsm[d] = g_gpool[g * 64 + d];
    __syncthreads();
    float acc = fc1b[d];
    for (int k = 0; k < 64; k++) acc = fmaf(gsm[k], g_fc1Wt[k * 64 + d], acc);
    tsm[d] = fmaxf(acc, 0.f);
    __syncthreads();
    if (d < OUTD) {
        float a2 = fc2b[d];
        for (int k = 0; k < 64; k++) a2 = fmaf(tsm[k], g_fc2Wt[k * 16 + d], a2);
        out[g * OUTD + d] = a2;
    }
}

// ---------------- host ----------------
extern "C" void kernel_launch(void* const* d_in, const int* in_sizes, int n_in,
                              void* d_out, int out_size) {
    const float* x    = (const float*)d_in[0];
    const int*   ei   = (const int*)d_in[1];
    const int*   src  = ei;
    const int*   dst  = ei + Ee;
    const int*   batch = (const int*)d_in[2];
    const float* encW = (const float*)d_in[3];
    const float* encb = (const float*)d_in[4];
    const float* nnW1 = (const float*)d_in[5];
    const float* nnb1 = (const float*)d_in[6];
    const float* nnW2 = (const float*)d_in[7];
    const float* nnb2 = (const float*)d_in[8];
    const float* mlpW = (const float*)d_in[9];
    const float* mlpb = (const float*)d_in[10];
    const float* bnG  = (const float*)d_in[11];
    const float* bnB  = (const float*)d_in[12];
    const float* fc1W = (const float*)d_in[13];
    const float* fc1b = (const float*)d_in[14];
    const float* fc2W = (const float*)d_in[15];
    const float* fc2b = (const float*)d_in[16];
    float* out = (float*)d_out;

    float *p_hA, *p_hB, *p_hC, *p_encWt, *p_nnW1t, *p_nnW2t, *p_mlpWt, *p_fc1Wt;
    cudaGetSymbolAddress((void**)&p_hA, g_hA);
    cudaGetSymbolAddress((void**)&p_hB, g_hB);
    cudaGetSymbolAddress((void**)&p_hC, g_hC);
    cudaGetSymbolAddress((void**)&p_encWt, g_encWt);
    cudaGetSymbolAddress((void**)&p_nnW1t, g_nnW1t);
    cudaGetSymbolAddress((void**)&p_nnW2t, g_nnW2t);
    cudaGetSymbolAddress((void**)&p_mlpWt, g_mlpWt);
    cudaGetSymbolAddress((void**)&p_fc1Wt, g_fc1Wt);

    const int NB_SCAN = (Nn + 1023) / 1024;  // 98

    // CSR build
    k_zero_deg<<<(Nn + 255) / 256, 256>>>();
    k_count<<<(Ee + 255) / 256, 256>>>(dst);
    k_scan_block<<<NB_SCAN, 1024>>>();
    k_scan_tops<<<1, 1>>>(NB_SCAN);
    k_rowptr<<<(Nn + 255) / 256, 256>>>();
    k_scatter<<<(Ee + 255) / 256, 256>>>(src, dst);
    k_sortrows<<<(Nn + 255) / 256, 256>>>();

    // transposes
    k_t64<<<(4096 + 255) / 256, 256>>>(encW, p_encWt, 1);
    k_t64<<<(5 * 4096 + 255) / 256, 256>>>(nnW1, p_nnW1t, 5);
    k_t64<<<(5 * 4096 + 255) / 256, 256>>>(nnW2, p_nnW2t, 5);
    k_t64<<<(4096 + 255) / 256, 256>>>(fc1W, p_fc1Wt, 1);
    k_tmlp<<<(NL * 49152 + 255) / 256, 256>>>(mlpW);
    k_tfc2<<<(Dd * OUTD + 255) / 256, 256>>>(fc2W);

    const int NBLIN = NnP / 64;   // 1563
    const int NBGS  = NnP / 48;   // 2084

    // encoder
    k_lin64<false><<<NBLIN, 64>>>(x, p_encWt, encb, p_hA);

    for (int i = 0; i < NL; i++) {
        k_agg<<<(Nn * 32 + 255) / 256, 256>>>();
        k_gemmS<<<NBGS, 192>>>(p_mlpWt + i * 49152);
        k_combine<<<(Nn * Dd + 255) / 256, 256>>>(mlpb + i * Dd);
        k_lin64<true><<<NBLIN, 64>>>(p_hB, p_nnW1t + i * 4096, nnb1 + i * Dd, p_hC);
        k_lin64<true><<<NBLIN, 64>>>(p_hC, p_nnW2t + i * 4096, nnb2 + i * Dd, p_hB);
        k_bnpart<<<Gg, 64>>>();
        k_bnfin<<<1, 64>>>(bnG + i * Dd, bnB + i * Dd);
        k_bnapply<<<(Nn * Dd + 255) / 256, 256>>>();
    }

    k_bounds<<<(Gg + 1 + 255) / 256, 256>>>(batch);
    k_pool<<<Gg, 64>>>();
    k_head<<<Gg, 64>>>(fc1b, fc2b, out);
}

// round 4
// speedup vs baseline: 1.7620x; 1.7620x over previous
#include <cuda_runtime.h>
#include <cfloat>
#include <cstdint>

#define Nn 100000
#define NnP 100096          // multiple of 128 (MMA tile) and 64
#define Ee 1600000
#define Dd 64
#define Gg 512
#define OUTD 16
#define NL 5
#define DELTA 2.5749f
#define BN_EPS 1e-5f

// ---------------- static device scratch ----------------
static __device__ float g_hA[NnP * Dd];
static __device__ float g_hB[NnP * Dd];
static __device__ float g_hC[NnP * Dd];
static __device__ float g_base[NnP * 256];     // [sum|max|mean|var]
static __device__ float g_cfac[NnP];
static __device__ int   g_deg[Nn];
static __device__ int   g_sc[Nn];
static __device__ int   g_bsum[128];
static __device__ int   g_rowptr[Nn + 1];
static __device__ int   g_cursor[Nn];
static __device__ int   g_esrc[Ee];
static __device__ float g_part[Gg * 2 * Dd];
static __device__ float g_scale[Dd];
static __device__ float g_shift[Dd];
static __device__ int   g_bstart[Gg + 1];
static __device__ float g_gpool[Gg * Dd];
static __device__ float g_encWt[Dd * Dd];
static __device__ float g_nnW1t[NL * Dd * Dd];
static __device__ float g_nnW2t[NL * Dd * Dd];
static __device__ float g_mlpBh[NL * 256 * 192];  // [k][n], tf32 hi
static __device__ float g_mlpBl[NL * 256 * 192];  // [k][n], tf32 lo residual
static __device__ float g_fc1Wt[Dd * Dd];
static __device__ float g_fc2Wt[Dd * OUTD];

__device__ __forceinline__ float tf32r(float x) {
    float y;
    asm("cvt.rna.tf32.f32 %0, %1;" : "=f"(y) : "f"(x));
    return y;
}
__device__ __forceinline__ void mma1688(float* c, const uint32_t* a, uint32_t b0, uint32_t b1) {
    asm volatile(
        "mma.sync.aligned.m16n8k8.row.col.f32.tf32.tf32.f32 "
        "{%0,%1,%2,%3}, {%4,%5,%6,%7}, {%8,%9}, {%0,%1,%2,%3};"
        : "+f"(c[0]), "+f"(c[1]), "+f"(c[2]), "+f"(c[3])
        : "r"(a[0]), "r"(a[1]), "r"(a[2]), "r"(a[3]), "r"(b0), "r"(b1));
}

// ---------------- CSR build ----------------
__global__ void k_zero_deg() {
    int i = blockIdx.x * blockDim.x + threadIdx.x;
    if (i < Nn) g_deg[i] = 0;
}
__global__ void k_count(const int* __restrict__ dst) {
    int e = blockIdx.x * blockDim.x + threadIdx.x;
    if (e < Ee) atomicAdd(&g_deg[dst[e]], 1);
}
__global__ void k_scan_block() {
    __shared__ int sm[1024];
    int i = blockIdx.x * 1024 + threadIdx.x;
    int v = (i < Nn) ? g_deg[i] : 0;
    sm[threadIdx.x] = v;
    __syncthreads();
    for (int off = 1; off < 1024; off <<= 1) {
        int t = 0;
        if (threadIdx.x >= off) t = sm[threadIdx.x - off];
        __syncthreads();
        sm[threadIdx.x] += t;
        __syncthreads();
    }
    if (i < Nn) g_sc[i] = sm[threadIdx.x];
    if (threadIdx.x == 1023) g_bsum[blockIdx.x] = sm[1023];
}
__global__ void k_scan_tops(int nb) {
    if (threadIdx.x == 0 && blockIdx.x == 0) {
        int run = 0;
        for (int b = 0; b < nb; b++) { int t = g_bsum[b]; g_bsum[b] = run; run += t; }
    }
}
__global__ void k_rowptr() {
    int i = blockIdx.x * blockDim.x + threadIdx.x;
    if (i < Nn) {
        int rp = g_sc[i] - g_deg[i] + g_bsum[i >> 10];
        g_rowptr[i] = rp;
        g_cursor[i] = rp;
    }
    if (i == 0) g_rowptr[Nn] = Ee;
}
__global__ void k_scatter(const int* __restrict__ src, const int* __restrict__ dst) {
    int e = blockIdx.x * blockDim.x + threadIdx.x;
    if (e < Ee) {
        int p = atomicAdd(&g_cursor[dst[e]], 1);
        g_esrc[p] = src[e];
    }
}
__global__ void k_sortrows() {
    int n = blockIdx.x * blockDim.x + threadIdx.x;
    if (n >= Nn) return;
    int beg = g_rowptr[n], end = g_rowptr[n + 1];
    for (int i = beg + 1; i < end; i++) {
        int v = g_esrc[i];
        int j = i - 1;
        while (j >= beg && g_esrc[j] > v) { g_esrc[j + 1] = g_esrc[j]; j--; }
        g_esrc[j + 1] = v;
    }
    g_cfac[n] = fmaxf((float)(end - beg), 1.0f);
}

// ---------------- weight prep ----------------
__global__ void k_t64(const float* __restrict__ W, float* __restrict__ Wt, int nm) {
    int idx = blockIdx.x * blockDim.x + threadIdx.x;
    if (idx >= nm * 4096) return;
    int m = idx >> 12, r = idx & 4095;
    int d = r >> 6, k = r & 63;
    Wt[(m << 12) + (k << 6) + d] = W[idx];
}
// g_mlpB{h,l}[m][k*192+n] from mlpW[m][(n&63)*768 + (n>>6)*256 + k]
__global__ void k_tmlpB(const float* __restrict__ W) {
    int idx = blockIdx.x * blockDim.x + threadIdx.x;
    if (idx >= NL * 256 * 192) return;
    int m = idx / 49152, r = idx % 49152;
    int k = r / 192, n = r % 192;
    int d = n & 63, b = n >> 6;
    float w = W[m * 49152 + d * 768 + b * 256 + k];
    float h = tf32r(w);
    g_mlpBh[idx] = h;
    g_mlpBl[idx] = tf32r(w - h);
}
__global__ void k_tfc2(const float* __restrict__ W) {
    int idx = blockIdx.x * blockDim.x + threadIdx.x;
    if (idx >= Dd * OUTD) return;
    int o = idx >> 6, k = idx & 63;
    g_fc2Wt[k * 16 + o] = W[idx];
}

// ---------------- 64x64 linear ----------------
template <bool RELU>
__global__ void __launch_bounds__(64) k_lin64(const float* __restrict__ A,
                                              const float* __restrict__ Wt,
                                              const float* __restrict__ b,
                                              float* __restrict__ C) {
    __shared__ float4 Asm[64][16];
    int row0 = blockIdx.x * 64, tid = threadIdx.x;
    for (int t = tid; t < 1024; t += 64) {
        int r = t >> 4, c = t & 15;
        float4 v = make_float4(0.f, 0.f, 0.f, 0.f);
        if (row0 + r < Nn) v = ((const float4*)A)[(row0 + r) * 16 + c];
        Asm[r][c] = v;
    }
    __syncthreads();
    float acc[64];
#pragma unroll
    for (int r = 0; r < 64; r++) acc[r] = 0.f;
#pragma unroll 1
    for (int k4 = 0; k4 < 16; k4++) {
        float w0 = Wt[(k4 * 4 + 0) * 64 + tid];
        float w1 = Wt[(k4 * 4 + 1) * 64 + tid];
        float w2 = Wt[(k4 * 4 + 2) * 64 + tid];
        float w3 = Wt[(k4 * 4 + 3) * 64 + tid];
#pragma unroll
        for (int r = 0; r < 64; r++) {
            float4 a = Asm[r][k4];
            float t0 = fmaf(a.x, w0, acc[r]);
            t0 = fmaf(a.y, w1, t0);
            t0 = fmaf(a.z, w2, t0);
            acc[r] = fmaf(a.w, w3, t0);
        }
    }
    float bb = b[tid];
    for (int r = 0; r < 64; r++) {
        if (row0 + r < Nn) {
            float v = acc[r] + bb;
            if (RELU) v = fmaxf(v, 0.f);
            C[(row0 + r) * 64 + tid] = v;
        }
    }
}

// ---------------- PNA aggregation ----------------
__global__ void k_agg() {
    int gt = blockIdx.x * blockDim.x + threadIdx.x;
    int w = gt >> 5, lane = gt & 31;
    if (w >= Nn) return;
    int beg = g_rowptr[w], end = g_rowptr[w + 1];
    const float2* hp = (const float2*)g_hA;
    float sx = 0.f, sy = 0.f, qx = 0.f, qy = 0.f;
    float mxx = -FLT_MAX, mxy = -FLT_MAX;
    for (int j = beg; j < end; j++) {
        int s = g_esrc[j];
        float2 v = hp[s * 32 + lane];
        sx += v.x; sy += v.y;
        qx = fmaf(v.x, v.x, qx);
        qy = fmaf(v.y, v.y, qy);
        mxx = fmaxf(mxx, v.x);
        mxy = fmaxf(mxy, v.y);
    }
    if (end == beg) { mxx = 0.f; mxy = 0.f; }
    float c = g_cfac[w];
    float inv = 1.f / c;
    float mex = sx * inv, mey = sy * inv;
    float vx = fmaxf(qx * inv - mex * mex, 0.f);
    float vy = fmaxf(qy * inv - mey * mey, 0.f);
    float2* bp = (float2*)(g_base + (size_t)w * 256);
    bp[lane]      = make_float2(sx, sy);
    bp[32 + lane] = make_float2(mxx, mxy);
    bp[64 + lane] = make_float2(mex, mey);
    bp[96 + lane] = make_float2(vx, vy);
}

// ---------------- 3xTF32 mma.sync GEMM + fused combine ----------------
// S[128,192] = base[128,256] @ B[256,192] with error compensation:
// S = Ah*Bh + Ah*Bl + Al*Bh  (Al*Bl dropped, O(2^-22))
// CTA: 128x192, 384 threads = 12 warps (4m x 3n), warp tile 32x64.
#define AS_STRIDE 36
#define BS_STRIDE 200
#define SS_STRIDE 200
#define AH_OFFS 0
#define AL_OFFS (128 * AS_STRIDE)              // 4608
#define BH_OFFS (2 * 128 * AS_STRIDE)          // 9216
#define BL_OFFS (BH_OFFS + 32 * BS_STRIDE)     // 15616
#define MMA_SMEM_FLOATS (128 * SS_STRIDE)      // 25600 floats = 102400 B (covers 22016 mainloop)
#define MMA_SMEM_BYTES (MMA_SMEM_FLOATS * 4)

__global__ void __launch_bounds__(384)
k_pna_mma(const float* __restrict__ Bh, const float* __restrict__ Bl,
          const float* __restrict__ mb) {
    extern __shared__ float sm[];
    float* Ash = sm + AH_OFFS;
    float* Asl = sm + AL_OFFS;
    float* Bsh = sm + BH_OFFS;
    float* Bsl = sm + BL_OFFS;
    int tid = threadIdx.x, wid = tid >> 5, lane = tid & 31;
    int gid = lane >> 2, tig = lane & 3;
    int row0 = blockIdx.x * 128;
    int mrow0 = (wid & 3) * 32;
    int ncol0 = (wid >> 2) * 64;

    float acc[2][8][4];
#pragma unroll
    for (int mt = 0; mt < 2; mt++)
#pragma unroll
        for (int nt = 0; nt < 8; nt++)
#pragma unroll
            for (int j = 0; j < 4; j++) acc[mt][nt][j] = 0.f;

#pragma unroll 1
    for (int kc = 0; kc < 8; kc++) {
        // A chunk: 128 rows x 32 k, split hi/lo
        for (int i = tid; i < 1024; i += 384) {
            int r = i >> 3, c4 = i & 7;
            float4 v = *(const float4*)&g_base[(size_t)(row0 + r) * 256 + kc * 32 + c4 * 4];
            float4 h, l;
            h.x = tf32r(v.x); l.x = tf32r(v.x - h.x);
            h.y = tf32r(v.y); l.y = tf32r(v.y - h.y);
            h.z = tf32r(v.z); l.z = tf32r(v.z - h.z);
            h.w = tf32r(v.w); l.w = tf32r(v.w - h.w);
            *(float4*)&Ash[r * AS_STRIDE + c4 * 4] = h;
            *(float4*)&Asl[r * AS_STRIDE + c4 * 4] = l;
        }
        // B chunk: 32 k x 192 n, hi + lo (pre-split)
        for (int i = tid; i < 1536; i += 384) {
            int r = i / 48, c4 = i % 48;
            size_t go = (size_t)(kc * 32 + r) * 192 + c4 * 4;
            *(float4*)&Bsh[r * BS_STRIDE + c4 * 4] = *(const float4*)&Bh[go];
            *(float4*)&Bsl[r * BS_STRIDE + c4 * 4] = *(const float4*)&Bl[go];
        }
        __syncthreads();
#pragma unroll
        for (int k8 = 0; k8 < 4; k8++) {
            int kb = k8 * 8;
            uint32_t ah[2][4], al[2][4];
#pragma unroll
            for (int mt = 0; mt < 2; mt++) {
                int mr = mrow0 + mt * 16 + gid;
                ah[mt][0] = __float_as_uint(Ash[mr * AS_STRIDE + kb + tig]);
                ah[mt][1] = __float_as_uint(Ash[(mr + 8) * AS_STRIDE + kb + tig]);
                ah[mt][2] = __float_as_uint(Ash[mr * AS_STRIDE + kb + tig + 4]);
                ah[mt][3] = __float_as_uint(Ash[(mr + 8) * AS_STRIDE + kb + tig + 4]);
                al[mt][0] = __float_as_uint(Asl[mr * AS_STRIDE + kb + tig]);
                al[mt][1] = __float_as_uint(Asl[(mr + 8) * AS_STRIDE + kb + tig]);
                al[mt][2] = __float_as_uint(Asl[mr * AS_STRIDE + kb + tig + 4]);
                al[mt][3] = __float_as_uint(Asl[(mr + 8) * AS_STRIDE + kb + tig + 4]);
            }
#pragma unroll
            for (int nt = 0; nt < 8; nt++) {
                int nc = ncol0 + nt * 8 + gid;
                uint32_t bh0 = __float_as_uint(Bsh[(kb + tig) * BS_STRIDE + nc]);
                uint32_t bh1 = __float_as_uint(Bsh[(kb + tig + 4) * BS_STRIDE + nc]);
                uint32_t bl0 = __float_as_uint(Bsl[(kb + tig) * BS_STRIDE + nc]);
                uint32_t bl1 = __float_as_uint(Bsl[(kb + tig + 4) * BS_STRIDE + nc]);
                mma1688(acc[0][nt], ah[0], bh0, bh1);
                mma1688(acc[0][nt], ah[0], bl0, bl1);
                mma1688(acc[0][nt], al[0], bh0, bh1);
                mma1688(acc[1][nt], ah[1], bh0, bh1);
                mma1688(acc[1][nt], ah[1], bl0, bl1);
                mma1688(acc[1][nt], al[1], bh0, bh1);
            }
        }
        __syncthreads();
    }

    // stage S into smem (reuse whole buffer)
#pragma unroll
    for (int mt = 0; mt < 2; mt++) {
#pragma unroll
        for (int nt = 0; nt < 8; nt++) {
            int r = mrow0 + mt * 16 + gid;
            int c = ncol0 + nt * 8 + tig * 2;
            *(float2*)&sm[r * SS_STRIDE + c] = make_float2(acc[mt][nt][0], acc[mt][nt][1]);
            *(float2*)&sm[(r + 8) * SS_STRIDE + c] = make_float2(acc[mt][nt][2], acc[mt][nt][3]);
        }
    }
    __syncthreads();

    // fused combine epilogue
    for (int i = tid; i < 128 * 64; i += 384) {
        int r = i >> 6, d = i & 63;
        int row = row0 + r;
        if (row < Nn) {
            float cf = g_cfac[row];
            float aa = cf * (1.0f / DELTA);
            float b2 = DELTA / cf;
            const float* Sr = sm + r * SS_STRIDE;
            float v = g_hA[(size_t)row * 64 + d] + mb[d]
                    + Sr[d] + aa * Sr[64 + d] + b2 * Sr[128 + d];
            g_hB[(size_t)row * 64 + d] = v;
        }
    }
}

// ---------------- batchnorm ----------------
#define BN_CHUNK ((Nn + Gg - 1) / Gg)
__global__ void k_bnpart() {
    int b = blockIdx.x, d = threadIdx.x;
    int r0 = b * BN_CHUNK;
    int r1 = min(r0 + BN_CHUNK, Nn);
    float s = 0.f, q = 0.f;
    for (int r = r0; r < r1; r++) {
        float v = g_hB[r * 64 + d];
        s += v;
        q = fmaf(v, v, q);
    }
    g_part[b * 128 + d] = s;
    g_part[b * 128 + 64 + d] = q;
}
__global__ void k_bnfin(const float* __restrict__ gamma, const float* __restrict__ beta) {
    int d = threadIdx.x;
    float s = 0.f, q = 0.f;
    for (int b = 0; b < Gg; b++) {
        s += g_part[b * 128 + d];
        q += g_part[b * 128 + 64 + d];
    }
    float mean = s * (1.0f / Nn);
    float var = q * (1.0f / Nn) - mean * mean;
    float sc = gamma[d] * rsqrtf(var + BN_EPS);
    g_scale[d] = sc;
    g_shift[d] = fmaf(-mean, sc, beta[d]);
}
__global__ void k_bnapply() {
    int idx = blockIdx.x * blockDim.x + threadIdx.x;
    if (idx >= Nn * Dd) return;
    int d = idx & 63;
    g_hA[idx] = fmaf(g_hB[idx], g_scale[d], g_shift[d]);
}

// ---------------- pooling + head ----------------
__global__ void k_bounds(const int* __restrict__ batch) {
    int g = blockIdx.x * blockDim.x + threadIdx.x;
    if (g > Gg) return;
    if (g == Gg) { g_bstart[Gg] = Nn; return; }
    int lo = 0, hi = Nn;
    while (lo < hi) {
        int mid = (lo + hi) >> 1;
        if (batch[mid] < g) lo = mid + 1; else hi = mid;
    }
    g_bstart[g] = lo;
}
__global__ void k_pool() {
    int g = blockIdx.x, d = threadIdx.x;
    int r0 = g_bstart[g], r1 = g_bstart[g + 1];
    float s = 0.f;
    for (int r = r0; r < r1; r++) s += g_hA[r * 64 + d];
    g_gpool[g * 64 + d] = s;
}
__global__ void k_head(const float* __restrict__ fc1b, const float* __restrict__ fc2b,
                       float* __restrict__ out) {
    __shared__ float gsm[64], tsm[64];
    int g = blockIdx.x, d = threadIdx.x;
    gsm[d] = g_gpool[g * 64 + d];
    __syncthreads();
    float acc = fc1b[d];
    for (int k = 0; k < 64; k++) acc = fmaf(gsm[k], g_fc1Wt[k * 64 + d], acc);
    tsm[d] = fmaxf(acc, 0.f);
    __syncthreads();
    if (d < OUTD) {
        float a2 = fc2b[d];
        for (int k = 0; k < 64; k++) a2 = fmaf(tsm[k], g_fc2Wt[k * 16 + d], a2);
        out[g * OUTD + d] = a2;
    }
}

// ---------------- host ----------------
extern "C" void kernel_launch(void* const* d_in, const int* in_sizes, int n_in,
                              void* d_out, int out_size) {
    const float* x    = (const float*)d_in[0];
    const int*   ei   = (const int*)d_in[1];
    const int*   src  = ei;
    const int*   dst  = ei + Ee;
    const int*   batch = (const int*)d_in[2];
    const float* encW = (const float*)d_in[3];
    const float* encb = (const float*)d_in[4];
    const float* nnW1 = (const float*)d_in[5];
    const float* nnb1 = (const float*)d_in[6];
    const float* nnW2 = (const float*)d_in[7];
    const float* nnb2 = (const float*)d_in[8];
    const float* mlpW = (const float*)d_in[9];
    const float* mlpb = (const float*)d_in[10];
    const float* bnG  = (const float*)d_in[11];
    const float* bnB  = (const float*)d_in[12];
    const float* fc1W = (const float*)d_in[13];
    const float* fc1b = (const float*)d_in[14];
    const float* fc2W = (const float*)d_in[15];
    const float* fc2b = (const float*)d_in[16];
    float* out = (float*)d_out;

    float *p_hA, *p_hB, *p_hC, *p_encWt, *p_nnW1t, *p_nnW2t, *p_mlpBh, *p_mlpBl, *p_fc1Wt;
    cudaGetSymbolAddress((void**)&p_hA, g_hA);
    cudaGetSymbolAddress((void**)&p_hB, g_hB);
    cudaGetSymbolAddress((void**)&p_hC, g_hC);
    cudaGetSymbolAddress((void**)&p_encWt, g_encWt);
    cudaGetSymbolAddress((void**)&p_nnW1t, g_nnW1t);
    cudaGetSymbolAddress((void**)&p_nnW2t, g_nnW2t);
    cudaGetSymbolAddress((void**)&p_mlpBh, g_mlpBh);
    cudaGetSymbolAddress((void**)&p_mlpBl, g_mlpBl);
    cudaGetSymbolAddress((void**)&p_fc1Wt, g_fc1Wt);

    cudaFuncSetAttribute(k_pna_mma, cudaFuncAttributeMaxDynamicSharedMemorySize, MMA_SMEM_BYTES);

    const int NB_SCAN = (Nn + 1023) / 1024;

    // CSR build
    k_zero_deg<<<(Nn + 255) / 256, 256>>>();
    k_count<<<(Ee + 255) / 256, 256>>>(dst);
    k_scan_block<<<NB_SCAN, 1024>>>();
    k_scan_tops<<<1, 1>>>(NB_SCAN);
    k_rowptr<<<(Nn + 255) / 256, 256>>>();
    k_scatter<<<(Ee + 255) / 256, 256>>>(src, dst);
    k_sortrows<<<(Nn + 255) / 256, 256>>>();

    // weight prep
    k_t64<<<(4096 + 255) / 256, 256>>>(encW, p_encWt, 1);
    k_t64<<<(5 * 4096 + 255) / 256, 256>>>(nnW1, p_nnW1t, 5);
    k_t64<<<(5 * 4096 + 255) / 256, 256>>>(nnW2, p_nnW2t, 5);
    k_t64<<<(4096 + 255) / 256, 256>>>(fc1W, p_fc1Wt, 1);
    k_tmlpB<<<(NL * 256 * 192 + 255) / 256, 256>>>(mlpW);
    k_tfc2<<<(Dd * OUTD + 255) / 256, 256>>>(fc2W);

    const int NBLIN = NnP / 64;    // 1564
    const int NBMMA = NnP / 128;   // 782

    k_lin64<false><<<NBLIN, 64>>>(x, p_encWt, encb, p_hA);

    for (int i = 0; i < NL; i++) {
        k_agg<<<(Nn * 32 + 255) / 256, 256>>>();
        k_pna_mma<<<NBMMA, 384, MMA_SMEM_BYTES>>>(p_mlpBh + i * 49152, p_mlpBl + i * 49152, mlpb + i * Dd);
        k_lin64<true><<<NBLIN, 64>>>(p_hB, p_nnW1t + i * 4096, nnb1 + i * Dd, p_hC);
        k_lin64<true><<<NBLIN, 64>>>(p_hC, p_nnW2t + i * 4096, nnb2 + i * Dd, p_hB);
        k_bnpart<<<Gg, 64>>>();
        k_bnfin<<<1, 64>>>(bnG + i * Dd, bnB + i * Dd);
        k_bnapply<<<(Nn * Dd + 255) / 256, 256>>>();
    }

    k_bounds<<<(Gg + 1 + 255) / 256, 256>>>(batch);
    k_pool<<<Gg, 64>>>();
    k_head<<<Gg, 64>>>(fc1b, fc2b, out);
}